// round 16
// baseline (speedup 1.0000x reference)
#include <cuda_runtime.h>
#include <cuda_bf16.h>
#include <cstdint>

#define NB 2
#define NT 2048
#define NC 1024
#define NH 16
#define ND 64
#define NM (NB * NT)   // 4096

// ---------------------------------------------------------------------------
// Device-global scratch (allocation-free rule)
// ---------------------------------------------------------------------------
__device__ __nv_bfloat16 g_qh[(size_t)NB * NH * NT * ND];  // Q prescaled by 1/8*log2e
__device__ __nv_bfloat16 g_ql[(size_t)NB * NH * NT * ND];
__device__ __nv_bfloat16 g_kh[(size_t)NB * NH * NT * ND];
__device__ __nv_bfloat16 g_kl[(size_t)NB * NH * NT * ND];
__device__ __nv_bfloat16 g_vh[(size_t)NB * NH * NT * ND];
__device__ __nv_bfloat16 g_vl[(size_t)NB * NH * NT * ND];

__device__ __nv_bfloat16 g_xh[(size_t)NM * NC];
__device__ __nv_bfloat16 g_xl[(size_t)NM * NC];
__device__ __nv_bfloat16 g_wh[(size_t)3 * NH * ND * NC];  // [z][h][d][c]
__device__ __nv_bfloat16 g_wl[(size_t)3 * NH * ND * NC];
__device__ __nv_bfloat16 g_woh[(size_t)NC * NC];          // [o][c]
__device__ __nv_bfloat16 g_wol[(size_t)NC * NC];
__device__ __nv_bfloat16 g_ah[(size_t)NM * NC];           // attention out hi/lo
__device__ __nv_bfloat16 g_al[(size_t)NM * NC];

// ---------------------------------------------------------------------------
// Warp-MMA + async-copy helpers (sm_80+ ISA; compiles for plain sm_103)
// ---------------------------------------------------------------------------
__device__ __forceinline__ uint32_t smem_to_u32(const void* smem_ptr) {
    uint32_t addr;
    asm("{ .reg .u64 tmp; cvta.to.shared.u64 tmp, %1; cvt.u32.u64 %0, tmp; }"
        : "=r"(addr) : "l"(smem_ptr));
    return addr;
}

#define LDSM_X4(R0, R1, R2, R3, addr) \
    asm volatile("ldmatrix.sync.aligned.m8n8.x4.shared.b16 {%0,%1,%2,%3}, [%4];" \
        : "=r"(R0), "=r"(R1), "=r"(R2), "=r"(R3) : "r"(addr))

#define LDSM_X4_T(R0, R1, R2, R3, addr) \
    asm volatile("ldmatrix.sync.aligned.m8n8.x4.trans.shared.b16 {%0,%1,%2,%3}, [%4];" \
        : "=r"(R0), "=r"(R1), "=r"(R2), "=r"(R3) : "r"(addr))

#define CP_ASYNC16(saddr, gptr) \
    asm volatile("cp.async.cg.shared.global [%0], [%1], 16;" \
        :: "r"(saddr), "l"(gptr) : "memory")
#define CP_COMMIT() asm volatile("cp.async.commit_group;" ::: "memory")
#define CP_WAIT(n)  asm volatile("cp.async.wait_group %0;" :: "n"(n) : "memory")

__device__ __forceinline__ void mma_bf16(float* c, const uint32_t* a,
                                         uint32_t b0, uint32_t b1)
{
    asm volatile(
        "mma.sync.aligned.m16n8k16.row.col.f32.bf16.bf16.f32 "
        "{%0,%1,%2,%3}, {%4,%5,%6,%7}, {%8,%9}, {%0,%1,%2,%3};"
        : "+f"(c[0]), "+f"(c[1]), "+f"(c[2]), "+f"(c[3])
        : "r"(a[0]), "r"(a[1]), "r"(a[2]), "r"(a[3]), "r"(b0), "r"(b1));
}

// SW128-style xor swizzle for 128-byte rows
__device__ __forceinline__ uint32_t swz(uint32_t off) {
    return off ^ ((off >> 3) & 0x70);
}

// exp2 on the FMA pipe (no MUFU). |rel err| < 5e-5 on [-120, 0].
__device__ __forceinline__ float fexp2(float x) {
    x = fmaxf(x, -120.f);
    float n = rintf(x);
    float r = x - n;
    float p = 1.f + r * (0.6931471806f + r * (0.2402265070f + r * (0.0555041087f
                + r * (0.0096181291f + r * 0.0013333558f))));
    return __int_as_float(((int)n + 127) << 23) * p;
}

// split pair of floats into packed bf16 hi and lo
__device__ __forceinline__ void split2(float f0, float f1, uint32_t& hi, uint32_t& lo) {
    __nv_bfloat162 h2 = __floats2bfloat162_rn(f0, f1);
    float r0 = f0 - __bfloat162float(h2.x);
    float r1 = f1 - __bfloat162float(h2.y);
    __nv_bfloat162 l2 = __floats2bfloat162_rn(r0, r1);
    hi = *reinterpret_cast<uint32_t*>(&h2);
    lo = *reinterpret_cast<uint32_t*>(&l2);
}

// GEMM smem: 2 stages x (AH,AL,BH,BL @16KB each) = 128KB
#define SM_AH 0
#define SM_AL 16384
#define SM_BH 32768
#define SM_BL 49152
#define SM_STAGE 65536
#define SMEM_GEMM_TOTAL 131072

// ---------------------------------------------------------------------------
// bf16 split: f = hi + lo
// ---------------------------------------------------------------------------
__global__ __launch_bounds__(256) void split_kernel(
    const float* __restrict__ in, __nv_bfloat16* __restrict__ hi,
    __nv_bfloat16* __restrict__ lo, int n4)
{
    for (int i = blockIdx.x * blockDim.x + threadIdx.x; i < n4; i += gridDim.x * blockDim.x) {
        float4 v = ((const float4*)in)[i];
        uint32_t h0, l0, h1, l1;
        split2(v.x, v.y, h0, l0);
        split2(v.z, v.w, h1, l1);
        *(uint2*)(hi + (size_t)i * 4) = make_uint2(h0, h1);
        *(uint2*)(lo + (size_t)i * 4) = make_uint2(l0, l1);
    }
}

// ---------------------------------------------------------------------------
// W transpose + split: W[z][h][c][d] f32 -> g_wh/g_wl[z][h][d][c] bf16
// ---------------------------------------------------------------------------
__global__ void wtsplit_kernel(const float* __restrict__ Wq,
                               const float* __restrict__ Wk,
                               const float* __restrict__ Wv)
{
    __shared__ float tile[32][33];
    const int zh = blockIdx.z;
    const int z = zh >> 4;
    const float* W = (z == 0 ? Wq : (z == 1 ? Wk : Wv)) + (size_t)(zh & 15) * NC * ND;

    const int c0 = blockIdx.x * 32, d0 = blockIdx.y * 32;
    const int tx = threadIdx.x, ty = threadIdx.y;

#pragma unroll
    for (int j = 0; j < 32; j += 8)
        tile[ty + j][tx] = W[(size_t)(c0 + ty + j) * ND + d0 + tx];
    __syncthreads();

#pragma unroll
    for (int j = 0; j < 32; j += 8) {
        float f = tile[tx][ty + j];
        __nv_bfloat16 hv = __float2bfloat16_rn(f);
        __nv_bfloat16 lv = __float2bfloat16_rn(f - __bfloat162float(hv));
        size_t o = ((size_t)zh * ND + d0 + ty + j) * NC + c0 + tx;
        g_wh[o] = hv;
        g_wl[o] = lv;
    }
}

// ---------------------------------------------------------------------------
// Shared HMMA mainloop: 128x128 tile, cp.async 2-stage pipeline.
// ---------------------------------------------------------------------------
__device__ __forceinline__ void gemm_tile_mainloop(
    uint32_t smem_u32, int tid,
    const __nv_bfloat16* __restrict__ gAh, const __nv_bfloat16* __restrict__ gAl,
    const __nv_bfloat16* __restrict__ gBh, const __nv_bfloat16* __restrict__ gBl,
    float acc[4][4][4])
{
    const int wid  = tid >> 5;
    const int lane = tid & 31;
    const int wm0 = (wid >> 2) * 64;
    const int wn0 = (wid & 3) * 32;

    const int a_row_off = (lane & 7) + ((lane >> 3) & 1) * 8;
    const int a_kb_off  = ((lane >> 4) & 1) * 16;
    const int b_row_off = (lane & 7) + ((lane >> 4) & 1) * 8;
    const int b_kb_off  = ((lane >> 3) & 1) * 16;

    auto issue = [&](int kt, int st) {
        const int k0 = kt * 64;
        const uint32_t sb = smem_u32 + st * SM_STAGE;
#pragma unroll
        for (int u = tid; u < 1024; u += 256) {
            const int r = u >> 3, c = u & 7;
            const uint32_t sw = swz((uint32_t)(r << 7) + (uint32_t)(c << 4));
            const size_t gofs = (size_t)r * NC + k0 + c * 8;
            CP_ASYNC16(sb + SM_AH + sw, gAh + gofs);
            CP_ASYNC16(sb + SM_AL + sw, gAl + gofs);
            CP_ASYNC16(sb + SM_BH + sw, gBh + gofs);
            CP_ASYNC16(sb + SM_BL + sw, gBl + gofs);
        }
        CP_COMMIT();
    };

    issue(0, 0);
    issue(1, 1);

    for (int kt = 0; kt < 16; kt++) {
        if (kt == 15) { CP_WAIT(0); } else { CP_WAIT(1); }
        __syncthreads();
        const uint32_t sb = smem_u32 + (kt & 1) * SM_STAGE;

#pragma unroll
        for (int ks = 0; ks < 4; ks++) {
            const int kb = ks * 32;

            uint32_t ah[4][4], al[4][4];
#pragma unroll
            for (int mi = 0; mi < 4; mi++) {
                const int row = wm0 + mi * 16 + a_row_off;
                const uint32_t sw = swz((uint32_t)(row << 7) + (uint32_t)(kb + a_kb_off));
                LDSM_X4(ah[mi][0], ah[mi][1], ah[mi][2], ah[mi][3], sb + SM_AH + sw);
                LDSM_X4(al[mi][0], al[mi][1], al[mi][2], al[mi][3], sb + SM_AL + sw);
            }

            uint32_t bh[2][4], bl[2][4];
#pragma unroll
            for (int j = 0; j < 2; j++) {
                const int nrow = wn0 + j * 16 + b_row_off;
                const uint32_t sw = swz((uint32_t)(nrow << 7) + (uint32_t)(kb + b_kb_off));
                LDSM_X4(bh[j][0], bh[j][1], bh[j][2], bh[j][3], sb + SM_BH + sw);
                LDSM_X4(bl[j][0], bl[j][1], bl[j][2], bl[j][3], sb + SM_BL + sw);
            }

#pragma unroll
            for (int mi = 0; mi < 4; mi++) {
#pragma unroll
                for (int j = 0; j < 2; j++) {
#pragma unroll
                    for (int s = 0; s < 2; s++) {
                        const int nt = j * 2 + s;
                        mma_bf16(acc[mi][nt], ah[mi], bh[j][s * 2], bh[j][s * 2 + 1]);
                        mma_bf16(acc[mi][nt], ah[mi], bl[j][s * 2], bl[j][s * 2 + 1]);
                        mma_bf16(acc[mi][nt], al[mi], bh[j][s * 2], bh[j][s * 2 + 1]);
                    }
                }
            }
        }
        __syncthreads();
        if (kt + 2 < 16) issue(kt + 2, kt & 1);
    }
}

// ---------------------------------------------------------------------------
// QKV GEMM: grid (NM/128, NH/2, 3), block 256. Epilogue writes bf16 hi/lo.
// Q is prescaled by 1/sqrt(D) * log2(e) for log2-domain softmax.
// ---------------------------------------------------------------------------
__global__ __launch_bounds__(256) void qkv_gemm()
{
    extern __shared__ char smem[];
    const uint32_t smem_u32 = smem_to_u32(smem);
    const int tid = threadIdx.x, wid = tid >> 5, lane = tid & 31;

    const int m0 = blockIdx.x * 128;
    const int h0 = blockIdx.y * 2;
    const int z  = blockIdx.z;

    const size_t wofs = (size_t)(z * NH + h0) * ND * NC;

    float acc[4][4][4];
#pragma unroll
    for (int i = 0; i < 4; i++)
#pragma unroll
        for (int j = 0; j < 4; j++)
#pragma unroll
            for (int k = 0; k < 4; k++) acc[i][j][k] = 0.f;

    gemm_tile_mainloop(smem_u32, tid,
                       g_xh + (size_t)m0 * NC, g_xl + (size_t)m0 * NC,
                       g_wh + wofs, g_wl + wofs, acc);

    __nv_bfloat16 *oh, *ol;
    if (z == 0)      { oh = g_qh; ol = g_ql; }
    else if (z == 1) { oh = g_kh; ol = g_kl; }
    else             { oh = g_vh; ol = g_vl; }
    const float sc = (z == 0) ? 0.1803368801f : 1.f;  // 0.125 * log2(e)

    const int wm0 = (wid >> 2) * 64;
    const int wn0 = (wid & 3) * 32;

#pragma unroll
    for (int mi = 0; mi < 4; mi++) {
#pragma unroll
        for (int nt = 0; nt < 4; nt++) {
            const int nloc = wn0 + nt * 8 + (lane & 3) * 2;
            const int h = h0 + (nloc >> 6);
            const int d = nloc & 63;
#pragma unroll
            for (int half = 0; half < 2; half++) {
                const int m = m0 + wm0 + mi * 16 + (lane >> 2) + half * 8;
                const int b = m >> 11, t = m & (NT - 1);
                uint32_t hv, lv;
                split2(acc[mi][nt][half * 2] * sc, acc[mi][nt][half * 2 + 1] * sc, hv, lv);
                const size_t idx = (((size_t)(b * NH + h) * NT + t) * ND) + d;
                *(uint32_t*)(oh + idx) = hv;
                *(uint32_t*)(ol + idx) = lv;
            }
        }
    }
}

// ---------------------------------------------------------------------------
// Output projection GEMM: grid (NM/128, NC/128), block 256.
// ---------------------------------------------------------------------------
__global__ __launch_bounds__(256) void proj_gemm(float* __restrict__ out)
{
    extern __shared__ char smem[];
    const uint32_t smem_u32 = smem_to_u32(smem);
    const int tid = threadIdx.x, wid = tid >> 5, lane = tid & 31;

    const int m0 = blockIdx.x * 128;
    const int n0 = blockIdx.y * 128;

    float acc[4][4][4];
#pragma unroll
    for (int i = 0; i < 4; i++)
#pragma unroll
        for (int j = 0; j < 4; j++)
#pragma unroll
            for (int k = 0; k < 4; k++) acc[i][j][k] = 0.f;

    gemm_tile_mainloop(smem_u32, tid,
                       g_ah + (size_t)m0 * NC, g_al + (size_t)m0 * NC,
                       g_woh + (size_t)n0 * NC, g_wol + (size_t)n0 * NC, acc);

    const int wm0 = (wid >> 2) * 64;
    const int wn0 = (wid & 3) * 32;

#pragma unroll
    for (int mi = 0; mi < 4; mi++) {
#pragma unroll
        for (int nt = 0; nt < 4; nt++) {
            const int n = n0 + wn0 + nt * 8 + (lane & 3) * 2;
#pragma unroll
            for (int half = 0; half < 2; half++) {
                const int m = m0 + wm0 + mi * 16 + (lane >> 2) + half * 8;
                *(float2*)(out + (size_t)m * NC + n) =
                    make_float2(acc[mi][nt][half * 2], acc[mi][nt][half * 2 + 1]);
            }
        }
    }
}

// ---------------------------------------------------------------------------
// HMMA flash attention (bf16x3, log2-domain softmax, FMA exp2).
// grid (NT/128, NH, NB), block 256 (8 warps x m16). Key tiles of 64,
// K/V double-buffered via cp.async. Smem: Q 32KB + 2x32KB KV = 96KB.
// ---------------------------------------------------------------------------
#define ATT_QH 0
#define ATT_QL 16384
#define ATT_KV 32768     // stage base; within stage: KH 0, KL 8K, VH 16K, VL 24K
#define ATT_KH 0
#define ATT_KL 8192
#define ATT_VH 16384
#define ATT_VL 24576
#define ATT_STAGE 32768
#define ATT_SMEM 98304

__global__ __launch_bounds__(256, 2) void attn_mma()
{
    extern __shared__ char smem[];
    const uint32_t sbm = smem_to_u32(smem);
    const int tid = threadIdx.x, wid = tid >> 5, lane = tid & 31;
    const int b = blockIdx.z, h = blockIdx.y;
    const int bx = gridDim.x - 1 - blockIdx.x;   // heaviest q-tiles first
    const int q0 = bx * 128;

    const size_t bh = (size_t)(b * NH + h) * NT * ND;
    const __nv_bfloat16* qh = g_qh + bh + (size_t)q0 * ND;
    const __nv_bfloat16* ql = g_ql + bh + (size_t)q0 * ND;
    const __nv_bfloat16* kh = g_kh + bh;
    const __nv_bfloat16* kl = g_kl + bh;
    const __nv_bfloat16* vh = g_vh + bh;
    const __nv_bfloat16* vl = g_vl + bh;

    auto issue_kv = [&](int jt, int st) {
        const int j0 = jt * 64;
        const uint32_t sb = sbm + ATT_KV + st * ATT_STAGE;
#pragma unroll
        for (int u = tid; u < 512; u += 256) {
            const int r = u >> 3, c = u & 7;
            const uint32_t sw = swz((uint32_t)(r << 7) + (uint32_t)(c << 4));
            const size_t go = (size_t)(j0 + r) * ND + c * 8;
            CP_ASYNC16(sb + ATT_KH + sw, kh + go);
            CP_ASYNC16(sb + ATT_KL + sw, kl + go);
            CP_ASYNC16(sb + ATT_VH + sw, vh + go);
            CP_ASYNC16(sb + ATT_VL + sw, vl + go);
        }
        CP_COMMIT();
    };

    const int ntiles = 2 * bx + 2;
    issue_kv(0, 0);
    issue_kv(1, 1);

    // Load Q tile (128 rows x 128 B) swizzled — overlaps with KV cp.async
#pragma unroll
    for (int u = tid; u < 1024; u += 256) {
        const int r = u >> 3, c = u & 7;
        const uint32_t sw = swz((uint32_t)(r << 7) + (uint32_t)(c << 4));
        const size_t go = (size_t)r * ND + c * 8;
        *(uint4*)(smem + ATT_QH + sw) = *(const uint4*)(qh + go);
        *(uint4*)(smem + ATT_QL + sw) = *(const uint4*)(ql + go);
    }

    float oacc[8][4];
#pragma unroll
    for (int j = 0; j < 8; j++)
#pragma unroll
        for (int k = 0; k < 4; k++) oacc[j][k] = 0.f;
    float mrow[2] = {-1e30f, -1e30f};
    float lrow[2] = {0.f, 0.f};

    const int a_row_off = (lane & 7) + ((lane >> 3) & 1) * 8;
    const int a_kb_off  = ((lane >> 4) & 1) * 16;
    const int b_row_off = (lane & 7) + ((lane >> 4) & 1) * 8;
    const int b_kb_off  = ((lane >> 3) & 1) * 16;
    const int v_s_off   = (lane & 7) + ((lane >> 3) & 1) * 8;
    const int v_d_off   = ((lane >> 4) & 1) * 16;

    const int wrow = q0 + wid * 16;           // warp's first query row

    for (int jt = 0; jt < ntiles; jt++) {
        const int j0 = jt * 64;
        if (jt == ntiles - 1) { CP_WAIT(0); } else { CP_WAIT(1); }
        __syncthreads();
        const uint32_t sb = sbm + ATT_KV + (jt & 1) * ATT_STAGE;

        if (j0 <= wrow + 15) {  // not fully masked for this warp (uniform)
            // ---- S = Q K^T (bf16x3), log2 domain (Q prescaled) ----
            float sacc[8][4];
#pragma unroll
            for (int j = 0; j < 8; j++)
#pragma unroll
                for (int k = 0; k < 4; k++) sacc[j][k] = 0.f;

#pragma unroll
            for (int ks = 0; ks < 4; ks++) {
                const int kb = ks * 32;
                uint32_t aqh[4], aql[4];
                const uint32_t swA = swz((uint32_t)((wid * 16 + a_row_off) << 7)
                                         + (uint32_t)(kb + a_kb_off));
                LDSM_X4(aqh[0], aqh[1], aqh[2], aqh[3], sbm + ATT_QH + swA);
                LDSM_X4(aql[0], aql[1], aql[2], aql[3], sbm + ATT_QL + swA);
#pragma unroll
                for (int jp = 0; jp < 4; jp++) {
                    uint32_t bkh[4], bkl[4];
                    const uint32_t swB = swz((uint32_t)((jp * 16 + b_row_off) << 7)
                                             + (uint32_t)(kb + b_kb_off));
                    LDSM_X4(bkh[0], bkh[1], bkh[2], bkh[3], sb + ATT_KH + swB);
                    LDSM_X4(bkl[0], bkl[1], bkl[2], bkl[3], sb + ATT_KL + swB);
#pragma unroll
                    for (int s = 0; s < 2; s++) {
                        float* c = sacc[jp * 2 + s];
                        mma_bf16(c, aqh, bkh[s * 2], bkh[s * 2 + 1]);
                        mma_bf16(c, aqh, bkl[s * 2], bkl[s * 2 + 1]);
                        mma_bf16(c, aql, bkh[s * 2], bkh[s * 2 + 1]);
                    }
                }
            }

            // ---- causal mask (diagonal-straddling tiles only) ----
            if (j0 + 63 > wrow) {
                const int row0 = wrow + (lane >> 2);
#pragma unroll
                for (int j = 0; j < 8; j++) {
                    const int col = j0 + j * 8 + (lane & 3) * 2;
                    if (col > row0)         sacc[j][0] = -1e30f;
                    if (col + 1 > row0)     sacc[j][1] = -1e30f;
                    if (col > row0 + 8)     sacc[j][2] = -1e30f;
                    if (col + 1 > row0 + 8) sacc[j][3] = -1e30f;
                }
            }

            // ---- online softmax (log2 domain) ----
            float mx0 = -1e30f, mx1 = -1e30f;
#pragma unroll
            for (int j = 0; j < 8; j++) {
                mx0 = fmaxf(mx0, fmaxf(sacc[j][0], sacc[j][1]));
                mx1 = fmaxf(mx1, fmaxf(sacc[j][2], sacc[j][3]));
            }
            mx0 = fmaxf(mx0, __shfl_xor_sync(0xffffffffu, mx0, 1));
            mx0 = fmaxf(mx0, __shfl_xor_sync(0xffffffffu, mx0, 2));
            mx1 = fmaxf(mx1, __shfl_xor_sync(0xffffffffu, mx1, 1));
            mx1 = fmaxf(mx1, __shfl_xor_sync(0xffffffffu, mx1, 2));

            const float nm0 = fmaxf(mrow[0], mx0);
            const float nm1 = fmaxf(mrow[1], mx1);
            const float corr0 = fexp2(mrow[0] - nm0);
            const float corr1 = fexp2(mrow[1] - nm1);
            mrow[0] = nm0; mrow[1] = nm1;

            float sum0 = 0.f, sum1 = 0.f;
#pragma unroll
            for (int j = 0; j < 8; j++) {
                sacc[j][0] = fexp2(sacc[j][0] - nm0);
                sacc[j][1] = fexp2(sacc[j][1] - nm0);
                sacc[j][2] = fexp2(sacc[j][2] - nm1);
                sacc[j][3] = fexp2(sacc[j][3] - nm1);
                sum0 += sacc[j][0] + sacc[j][1];
                sum1 += sacc[j][2] + sacc[j][3];
            }
            sum0 += __shfl_xor_sync(0xffffffffu, sum0, 1);
            sum0 += __shfl_xor_sync(0xffffffffu, sum0, 2);
            sum1 += __shfl_xor_sync(0xffffffffu, sum1, 1);
            sum1 += __shfl_xor_sync(0xffffffffu, sum1, 2);
            lrow[0] = lrow[0] * corr0 + sum0;
            lrow[1] = lrow[1] * corr1 + sum1;

#pragma unroll
            for (int j = 0; j < 8; j++) {
                oacc[j][0] *= corr0; oacc[j][1] *= corr0;
                oacc[j][2] *= corr1; oacc[j][3] *= corr1;
            }

            // ---- O += P V (bf16x3, P packed from registers) ----
#pragma unroll
            for (int ks = 0; ks < 4; ks++) {
                uint32_t ph[4], pl[4];
                split2(sacc[2 * ks][0],     sacc[2 * ks][1],     ph[0], pl[0]);
                split2(sacc[2 * ks][2],     sacc[2 * ks][3],     ph[1], pl[1]);
                split2(sacc[2 * ks + 1][0], sacc[2 * ks + 1][1], ph[2], pl[2]);
                split2(sacc[2 * ks + 1][2], sacc[2 * ks + 1][3], ph[3], pl[3]);
#pragma unroll
                for (int ndp = 0; ndp < 4; ndp++) {
                    uint32_t bvh[4], bvl[4];
                    const uint32_t swV = swz((uint32_t)((ks * 16 + v_s_off) << 7)
                                             + (uint32_t)(ndp * 32 + v_d_off));
                    LDSM_X4_T(bvh[0], bvh[1], bvh[2], bvh[3], sb + ATT_VH + swV);
                    LDSM_X4_T(bvl[0], bvl[1], bvl[2], bvl[3], sb + ATT_VL + swV);
#pragma unroll
                    for (int s = 0; s < 2; s++) {
                        float* c = oacc[ndp * 2 + s];
                        mma_bf16(c, ph, bvh[s * 2], bvh[s * 2 + 1]);
                        mma_bf16(c, ph, bvl[s * 2], bvl[s * 2 + 1]);
                        mma_bf16(c, pl, bvh[s * 2], bvh[s * 2 + 1]);
                    }
                }
            }
        }

        __syncthreads();
        if (jt + 2 < ntiles) issue_kv(jt + 2, jt & 1);
    }

    // ---- epilogue: normalize, split to bf16 hi/lo, write concat layout ----
    const float inv0 = 1.f / lrow[0];
    const float inv1 = 1.f / lrow[1];
    const int row0 = q0 + wid * 16 + (lane >> 2);
#pragma unroll
    for (int j = 0; j < 8; j++) {
        const int c = h * ND + j * 8 + (lane & 3) * 2;
        uint32_t hv, lv;
        split2(oacc[j][0] * inv0, oacc[j][1] * inv0, hv, lv);
        size_t idx = ((size_t)b * NT + row0) * NC + c;
        *(uint32_t*)(g_ah + idx) = hv;
        *(uint32_t*)(g_al + idx) = lv;
        split2(oacc[j][2] * inv1, oacc[j][3] * inv1, hv, lv);
        idx = ((size_t)b * NT + row0 + 8) * NC + c;
        *(uint32_t*)(g_ah + idx) = hv;
        *(uint32_t*)(g_al + idx) = lv;
    }
}

// ---------------------------------------------------------------------------
extern "C" void kernel_launch(void* const* d_in, const int* in_sizes, int n_in,
                              void* d_out, int out_size)
{
    const float* x  = (const float*)d_in[0];
    const float* Wq = (const float*)d_in[1];
    const float* Wk = (const float*)d_in[2];
    const float* Wv = (const float*)d_in[3];
    const float* Wo = (const float*)d_in[4];
    float* out = (float*)d_out;
    (void)in_sizes; (void)n_in; (void)out_size;

    cudaFuncSetAttribute(qkv_gemm, cudaFuncAttributeMaxDynamicSharedMemorySize,
                         SMEM_GEMM_TOTAL);
    cudaFuncSetAttribute(proj_gemm, cudaFuncAttributeMaxDynamicSharedMemorySize,
                         SMEM_GEMM_TOTAL);
    cudaFuncSetAttribute(attn_mma, cudaFuncAttributeMaxDynamicSharedMemorySize,
                         ATT_SMEM);

    __nv_bfloat16 *xh, *xl, *woh, *wol;
    cudaGetSymbolAddress((void**)&xh,  g_xh);
    cudaGetSymbolAddress((void**)&xl,  g_xl);
    cudaGetSymbolAddress((void**)&woh, g_woh);
    cudaGetSymbolAddress((void**)&wol, g_wol);

    // Prep: bf16 splits (x, Wo) + W transpose-split
    split_kernel<<<2048, 256>>>(x, xh, xl, (NM * NC) / 4);
    split_kernel<<<1024, 256>>>(Wo, woh, wol, (NC * NC) / 4);
    wtsplit_kernel<<<dim3(NC / 32, ND / 32, 3 * NH), dim3(32, 8)>>>(Wq, Wk, Wv);

    // QKV projection (HMMA bf16x3, cp.async pipelined)
    qkv_gemm<<<dim3(NM / 128, NH / 2, 3), 256, SMEM_GEMM_TOTAL>>>();

    // Attention (HMMA bf16x3 flash, cp.async pipelined K/V)
    attn_mma<<<dim3(NT / 128, NH, NB), 256, ATT_SMEM>>>();

    // Output projection (HMMA bf16x3, cp.async pipelined)
    proj_gemm<<<dim3(NM / 128, NC / 128), 256, SMEM_GEMM_TOTAL>>>(out);
}

// round 17
// speedup vs baseline: 1.0092x; 1.0092x over previous
#include <cuda_runtime.h>
#include <cuda_bf16.h>
#include <cstdint>

#define NB 2
#define NT 2048
#define NC 1024
#define NH 16
#define ND 64
#define NM (NB * NT)   // 4096

// ---------------------------------------------------------------------------
// Device-global scratch (allocation-free rule)
// ---------------------------------------------------------------------------
__device__ __nv_bfloat16 g_qh[(size_t)NB * NH * NT * ND];  // Q prescaled by 1/8*log2e
__device__ __nv_bfloat16 g_ql[(size_t)NB * NH * NT * ND];
__device__ __nv_bfloat16 g_kh[(size_t)NB * NH * NT * ND];
__device__ __nv_bfloat16 g_kl[(size_t)NB * NH * NT * ND];
__device__ __nv_bfloat16 g_vh[(size_t)NB * NH * NT * ND];
__device__ __nv_bfloat16 g_vl[(size_t)NB * NH * NT * ND];

__device__ __nv_bfloat16 g_xh[(size_t)NM * NC];
__device__ __nv_bfloat16 g_xl[(size_t)NM * NC];
__device__ __nv_bfloat16 g_wh[(size_t)3 * NH * ND * NC];  // [z][h][d][c]
__device__ __nv_bfloat16 g_wl[(size_t)3 * NH * ND * NC];
__device__ __nv_bfloat16 g_woh[(size_t)NC * NC];          // [o][c]
__device__ __nv_bfloat16 g_wol[(size_t)NC * NC];
__device__ __nv_bfloat16 g_ah[(size_t)NM * NC];           // attention out hi/lo
__device__ __nv_bfloat16 g_al[(size_t)NM * NC];

// ---------------------------------------------------------------------------
// Warp-MMA + async-copy helpers (sm_80+ ISA; compiles for plain sm_103)
// ---------------------------------------------------------------------------
__device__ __forceinline__ uint32_t smem_to_u32(const void* smem_ptr) {
    uint32_t addr;
    asm("{ .reg .u64 tmp; cvta.to.shared.u64 tmp, %1; cvt.u32.u64 %0, tmp; }"
        : "=r"(addr) : "l"(smem_ptr));
    return addr;
}

#define LDSM_X4(R0, R1, R2, R3, addr) \
    asm volatile("ldmatrix.sync.aligned.m8n8.x4.shared.b16 {%0,%1,%2,%3}, [%4];" \
        : "=r"(R0), "=r"(R1), "=r"(R2), "=r"(R3) : "r"(addr))

#define LDSM_X4_T(R0, R1, R2, R3, addr) \
    asm volatile("ldmatrix.sync.aligned.m8n8.x4.trans.shared.b16 {%0,%1,%2,%3}, [%4];" \
        : "=r"(R0), "=r"(R1), "=r"(R2), "=r"(R3) : "r"(addr))

#define CP_ASYNC16(saddr, gptr) \
    asm volatile("cp.async.cg.shared.global [%0], [%1], 16;" \
        :: "r"(saddr), "l"(gptr) : "memory")
#define CP_COMMIT() asm volatile("cp.async.commit_group;" ::: "memory")
#define CP_WAIT(n)  asm volatile("cp.async.wait_group %0;" :: "n"(n) : "memory")

__device__ __forceinline__ void mma_bf16(float* c, const uint32_t* a,
                                         uint32_t b0, uint32_t b1)
{
    asm volatile(
        "mma.sync.aligned.m16n8k16.row.col.f32.bf16.bf16.f32 "
        "{%0,%1,%2,%3}, {%4,%5,%6,%7}, {%8,%9}, {%0,%1,%2,%3};"
        : "+f"(c[0]), "+f"(c[1]), "+f"(c[2]), "+f"(c[3])
        : "r"(a[0]), "r"(a[1]), "r"(a[2]), "r"(a[3]), "r"(b0), "r"(b1));
}

// SW128-style xor swizzle for 128-byte rows
__device__ __forceinline__ uint32_t swz(uint32_t off) {
    return off ^ ((off >> 3) & 0x70);
}

// exp2 on the FMA pipe (no MUFU). |rel err| < 5e-5 on [-120, 0].
__device__ __forceinline__ float fexp2(float x) {
    x = fmaxf(x, -120.f);
    float n = rintf(x);
    float r = x - n;
    float p = 1.f + r * (0.6931471806f + r * (0.2402265070f + r * (0.0555041087f
                + r * (0.0096181291f + r * 0.0013333558f))));
    return __int_as_float(((int)n + 127) << 23) * p;
}

// split pair of floats into packed bf16 hi and lo
__device__ __forceinline__ void split2(float f0, float f1, uint32_t& hi, uint32_t& lo) {
    __nv_bfloat162 h2 = __floats2bfloat162_rn(f0, f1);
    float r0 = f0 - __bfloat162float(h2.x);
    float r1 = f1 - __bfloat162float(h2.y);
    __nv_bfloat162 l2 = __floats2bfloat162_rn(r0, r1);
    hi = *reinterpret_cast<uint32_t*>(&h2);
    lo = *reinterpret_cast<uint32_t*>(&l2);
}

// GEMM smem: 2 stages x (AH,AL,BH,BL @16KB each) = 128KB
#define SM_AH 0
#define SM_AL 16384
#define SM_BH 32768
#define SM_BL 49152
#define SM_STAGE 65536
#define SMEM_GEMM_TOTAL 131072

// ---------------------------------------------------------------------------
// bf16 split: f = hi + lo
// ---------------------------------------------------------------------------
__global__ __launch_bounds__(256) void split_kernel(
    const float* __restrict__ in, __nv_bfloat16* __restrict__ hi,
    __nv_bfloat16* __restrict__ lo, int n4)
{
    for (int i = blockIdx.x * blockDim.x + threadIdx.x; i < n4; i += gridDim.x * blockDim.x) {
        float4 v = ((const float4*)in)[i];
        uint32_t h0, l0, h1, l1;
        split2(v.x, v.y, h0, l0);
        split2(v.z, v.w, h1, l1);
        *(uint2*)(hi + (size_t)i * 4) = make_uint2(h0, h1);
        *(uint2*)(lo + (size_t)i * 4) = make_uint2(l0, l1);
    }
}

// ---------------------------------------------------------------------------
// W transpose + split: W[z][h][c][d] f32 -> g_wh/g_wl[z][h][d][c] bf16
// ---------------------------------------------------------------------------
__global__ void wtsplit_kernel(const float* __restrict__ Wq,
                               const float* __restrict__ Wk,
                               const float* __restrict__ Wv)
{
    __shared__ float tile[32][33];
    const int zh = blockIdx.z;
    const int z = zh >> 4;
    const float* W = (z == 0 ? Wq : (z == 1 ? Wk : Wv)) + (size_t)(zh & 15) * NC * ND;

    const int c0 = blockIdx.x * 32, d0 = blockIdx.y * 32;
    const int tx = threadIdx.x, ty = threadIdx.y;

#pragma unroll
    for (int j = 0; j < 32; j += 8)
        tile[ty + j][tx] = W[(size_t)(c0 + ty + j) * ND + d0 + tx];
    __syncthreads();

#pragma unroll
    for (int j = 0; j < 32; j += 8) {
        float f = tile[tx][ty + j];
        __nv_bfloat16 hv = __float2bfloat16_rn(f);
        __nv_bfloat16 lv = __float2bfloat16_rn(f - __bfloat162float(hv));
        size_t o = ((size_t)zh * ND + d0 + ty + j) * NC + c0 + tx;
        g_wh[o] = hv;
        g_wl[o] = lv;
    }
}

// ---------------------------------------------------------------------------
// Shared HMMA mainloop: 128x128 tile, cp.async 2-stage pipeline.
// ---------------------------------------------------------------------------
__device__ __forceinline__ void gemm_tile_mainloop(
    uint32_t smem_u32, int tid,
    const __nv_bfloat16* __restrict__ gAh, const __nv_bfloat16* __restrict__ gAl,
    const __nv_bfloat16* __restrict__ gBh, const __nv_bfloat16* __restrict__ gBl,
    float acc[4][4][4])
{
    const int wid  = tid >> 5;
    const int lane = tid & 31;
    const int wm0 = (wid >> 2) * 64;
    const int wn0 = (wid & 3) * 32;

    const int a_row_off = (lane & 7) + ((lane >> 3) & 1) * 8;
    const int a_kb_off  = ((lane >> 4) & 1) * 16;
    const int b_row_off = (lane & 7) + ((lane >> 4) & 1) * 8;
    const int b_kb_off  = ((lane >> 3) & 1) * 16;

    auto issue = [&](int kt, int st) {
        const int k0 = kt * 64;
        const uint32_t sb = smem_u32 + st * SM_STAGE;
#pragma unroll
        for (int u = tid; u < 1024; u += 256) {
            const int r = u >> 3, c = u & 7;
            const uint32_t sw = swz((uint32_t)(r << 7) + (uint32_t)(c << 4));
            const size_t gofs = (size_t)r * NC + k0 + c * 8;
            CP_ASYNC16(sb + SM_AH + sw, gAh + gofs);
            CP_ASYNC16(sb + SM_AL + sw, gAl + gofs);
            CP_ASYNC16(sb + SM_BH + sw, gBh + gofs);
            CP_ASYNC16(sb + SM_BL + sw, gBl + gofs);
        }
        CP_COMMIT();
    };

    issue(0, 0);
    issue(1, 1);

    for (int kt = 0; kt < 16; kt++) {
        if (kt == 15) { CP_WAIT(0); } else { CP_WAIT(1); }
        __syncthreads();
        const uint32_t sb = smem_u32 + (kt & 1) * SM_STAGE;

#pragma unroll
        for (int ks = 0; ks < 4; ks++) {
            const int kb = ks * 32;

            uint32_t ah[4][4], al[4][4];
#pragma unroll
            for (int mi = 0; mi < 4; mi++) {
                const int row = wm0 + mi * 16 + a_row_off;
                const uint32_t sw = swz((uint32_t)(row << 7) + (uint32_t)(kb + a_kb_off));
                LDSM_X4(ah[mi][0], ah[mi][1], ah[mi][2], ah[mi][3], sb + SM_AH + sw);
                LDSM_X4(al[mi][0], al[mi][1], al[mi][2], al[mi][3], sb + SM_AL + sw);
            }

            uint32_t bh[2][4], bl[2][4];
#pragma unroll
            for (int j = 0; j < 2; j++) {
                const int nrow = wn0 + j * 16 + b_row_off;
                const uint32_t sw = swz((uint32_t)(nrow << 7) + (uint32_t)(kb + b_kb_off));
                LDSM_X4(bh[j][0], bh[j][1], bh[j][2], bh[j][3], sb + SM_BH + sw);
                LDSM_X4(bl[j][0], bl[j][1], bl[j][2], bl[j][3], sb + SM_BL + sw);
            }

#pragma unroll
            for (int mi = 0; mi < 4; mi++) {
#pragma unroll
                for (int j = 0; j < 2; j++) {
#pragma unroll
                    for (int s = 0; s < 2; s++) {
                        const int nt = j * 2 + s;
                        mma_bf16(acc[mi][nt], ah[mi], bh[j][s * 2], bh[j][s * 2 + 1]);
                        mma_bf16(acc[mi][nt], ah[mi], bl[j][s * 2], bl[j][s * 2 + 1]);
                        mma_bf16(acc[mi][nt], al[mi], bh[j][s * 2], bh[j][s * 2 + 1]);
                    }
                }
            }
        }
        __syncthreads();
        if (kt + 2 < 16) issue(kt + 2, kt & 1);
    }
}

// ---------------------------------------------------------------------------
// QKV GEMM: grid (NM/128, NH/2, 3), block 256. Epilogue writes bf16 hi/lo.
// Q is prescaled by 1/sqrt(D) * log2(e) for log2-domain softmax.
// ---------------------------------------------------------------------------
__global__ __launch_bounds__(256) void qkv_gemm()
{
    extern __shared__ char smem[];
    const uint32_t smem_u32 = smem_to_u32(smem);
    const int tid = threadIdx.x, wid = tid >> 5, lane = tid & 31;

    const int m0 = blockIdx.x * 128;
    const int h0 = blockIdx.y * 2;
    const int z  = blockIdx.z;

    const size_t wofs = (size_t)(z * NH + h0) * ND * NC;

    float acc[4][4][4];
#pragma unroll
    for (int i = 0; i < 4; i++)
#pragma unroll
        for (int j = 0; j < 4; j++)
#pragma unroll
            for (int k = 0; k < 4; k++) acc[i][j][k] = 0.f;

    gemm_tile_mainloop(smem_u32, tid,
                       g_xh + (size_t)m0 * NC, g_xl + (size_t)m0 * NC,
                       g_wh + wofs, g_wl + wofs, acc);

    __nv_bfloat16 *oh, *ol;
    if (z == 0)      { oh = g_qh; ol = g_ql; }
    else if (z == 1) { oh = g_kh; ol = g_kl; }
    else             { oh = g_vh; ol = g_vl; }
    const float sc = (z == 0) ? 0.1803368801f : 1.f;  // 0.125 * log2(e)

    const int wm0 = (wid >> 2) * 64;
    const int wn0 = (wid & 3) * 32;

#pragma unroll
    for (int mi = 0; mi < 4; mi++) {
#pragma unroll
        for (int nt = 0; nt < 4; nt++) {
            const int nloc = wn0 + nt * 8 + (lane & 3) * 2;
            const int h = h0 + (nloc >> 6);
            const int d = nloc & 63;
#pragma unroll
            for (int half = 0; half < 2; half++) {
                const int m = m0 + wm0 + mi * 16 + (lane >> 2) + half * 8;
                const int b = m >> 11, t = m & (NT - 1);
                uint32_t hv, lv;
                split2(acc[mi][nt][half * 2] * sc, acc[mi][nt][half * 2 + 1] * sc, hv, lv);
                const size_t idx = (((size_t)(b * NH + h) * NT + t) * ND) + d;
                *(uint32_t*)(oh + idx) = hv;
                *(uint32_t*)(ol + idx) = lv;
            }
        }
    }
}

// ---------------------------------------------------------------------------
// Output projection GEMM: grid (NM/128, NC/128), block 256.
// ---------------------------------------------------------------------------
__global__ __launch_bounds__(256) void proj_gemm(float* __restrict__ out)
{
    extern __shared__ char smem[];
    const uint32_t smem_u32 = smem_to_u32(smem);
    const int tid = threadIdx.x, wid = tid >> 5, lane = tid & 31;

    const int m0 = blockIdx.x * 128;
    const int n0 = blockIdx.y * 128;

    float acc[4][4][4];
#pragma unroll
    for (int i = 0; i < 4; i++)
#pragma unroll
        for (int j = 0; j < 4; j++)
#pragma unroll
            for (int k = 0; k < 4; k++) acc[i][j][k] = 0.f;

    gemm_tile_mainloop(smem_u32, tid,
                       g_ah + (size_t)m0 * NC, g_al + (size_t)m0 * NC,
                       g_woh + (size_t)n0 * NC, g_wol + (size_t)n0 * NC, acc);

    const int wm0 = (wid >> 2) * 64;
    const int wn0 = (wid & 3) * 32;

#pragma unroll
    for (int mi = 0; mi < 4; mi++) {
#pragma unroll
        for (int nt = 0; nt < 4; nt++) {
            const int n = n0 + wn0 + nt * 8 + (lane & 3) * 2;
#pragma unroll
            for (int half = 0; half < 2; half++) {
                const int m = m0 + wm0 + mi * 16 + (lane >> 2) + half * 8;
                *(float2*)(out + (size_t)m * NC + n) =
                    make_float2(acc[mi][nt][half * 2], acc[mi][nt][half * 2 + 1]);
            }
        }
    }
}

// ---------------------------------------------------------------------------
// HMMA flash attention (bf16x3, log2-domain softmax, FMA exp2).
// grid (NT/128, NH, NB), block 256 (8 warps x m16). Key tiles of 64,
// K/V double-buffered via cp.async. Smem: Q 32KB + 2x32KB KV = 96KB.
// ---------------------------------------------------------------------------
#define ATT_QH 0
#define ATT_QL 16384
#define ATT_KV 32768     // stage base; within stage: KH 0, KL 8K, VH 16K, VL 24K
#define ATT_KH 0
#define ATT_KL 8192
#define ATT_VH 16384
#define ATT_VL 24576
#define ATT_STAGE 32768
#define ATT_SMEM 98304

__global__ __launch_bounds__(256, 2) void attn_mma()
{
    extern __shared__ char smem[];
    const uint32_t sbm = smem_to_u32(smem);
    const int tid = threadIdx.x, wid = tid >> 5, lane = tid & 31;
    const int b = blockIdx.z, h = blockIdx.y;
    const int bx = gridDim.x - 1 - blockIdx.x;   // heaviest q-tiles first
    const int q0 = bx * 128;

    const size_t bh = (size_t)(b * NH + h) * NT * ND;
    const __nv_bfloat16* qh = g_qh + bh + (size_t)q0 * ND;
    const __nv_bfloat16* ql = g_ql + bh + (size_t)q0 * ND;
    const __nv_bfloat16* kh = g_kh + bh;
    const __nv_bfloat16* kl = g_kl + bh;
    const __nv_bfloat16* vh = g_vh + bh;
    const __nv_bfloat16* vl = g_vl + bh;

    auto issue_kv = [&](int jt, int st) {
        const int j0 = jt * 64;
        const uint32_t sb = sbm + ATT_KV + st * ATT_STAGE;
#pragma unroll
        for (int u = tid; u < 512; u += 256) {
            const int r = u >> 3, c = u & 7;
            const uint32_t sw = swz((uint32_t)(r << 7) + (uint32_t)(c << 4));
            const size_t go = (size_t)(j0 + r) * ND + c * 8;
            CP_ASYNC16(sb + ATT_KH + sw, kh + go);
            CP_ASYNC16(sb + ATT_KL + sw, kl + go);
            CP_ASYNC16(sb + ATT_VH + sw, vh + go);
            CP_ASYNC16(sb + ATT_VL + sw, vl + go);
        }
        CP_COMMIT();
    };

    const int ntiles = 2 * bx + 2;
    issue_kv(0, 0);
    issue_kv(1, 1);

    // Load Q tile (128 rows x 128 B) swizzled — overlaps with KV cp.async
#pragma unroll
    for (int u = tid; u < 1024; u += 256) {
        const int r = u >> 3, c = u & 7;
        const uint32_t sw = swz((uint32_t)(r << 7) + (uint32_t)(c << 4));
        const size_t go = (size_t)r * ND + c * 8;
        *(uint4*)(smem + ATT_QH + sw) = *(const uint4*)(qh + go);
        *(uint4*)(smem + ATT_QL + sw) = *(const uint4*)(ql + go);
    }

    float oacc[8][4];
#pragma unroll
    for (int j = 0; j < 8; j++)
#pragma unroll
        for (int k = 0; k < 4; k++) oacc[j][k] = 0.f;
    float mrow[2] = {-1e30f, -1e30f};
    float lrow[2] = {0.f, 0.f};

    const int a_row_off = (lane & 7) + ((lane >> 3) & 1) * 8;
    const int a_kb_off  = ((lane >> 4) & 1) * 16;
    const int b_row_off = (lane & 7) + ((lane >> 4) & 1) * 8;
    const int b_kb_off  = ((lane >> 3) & 1) * 16;
    const int v_s_off   = (lane & 7) + ((lane >> 3) & 1) * 8;
    const int v_d_off   = ((lane >> 4) & 1) * 16;

    const int wrow = q0 + wid * 16;           // warp's first query row

    for (int jt = 0; jt < ntiles; jt++) {
        const int j0 = jt * 64;
        if (jt == ntiles - 1) { CP_WAIT(0); } else { CP_WAIT(1); }
        __syncthreads();
        const uint32_t sb = sbm + ATT_KV + (jt & 1) * ATT_STAGE;

        if (j0 <= wrow + 15) {  // not fully masked for this warp (uniform)
            // ---- S = Q K^T (bf16x3), log2 domain (Q prescaled) ----
            float sacc[8][4];
#pragma unroll
            for (int j = 0; j < 8; j++)
#pragma unroll
                for (int k = 0; k < 4; k++) sacc[j][k] = 0.f;

#pragma unroll
            for (int ks = 0; ks < 4; ks++) {
                const int kb = ks * 32;
                uint32_t aqh[4], aql[4];
                const uint32_t swA = swz((uint32_t)((wid * 16 + a_row_off) << 7)
                                         + (uint32_t)(kb + a_kb_off));
                LDSM_X4(aqh[0], aqh[1], aqh[2], aqh[3], sbm + ATT_QH + swA);
                LDSM_X4(aql[0], aql[1], aql[2], aql[3], sbm + ATT_QL + swA);
#pragma unroll
                for (int jp = 0; jp < 4; jp++) {
                    uint32_t bkh[4], bkl[4];
                    const uint32_t swB = swz((uint32_t)((jp * 16 + b_row_off) << 7)
                                             + (uint32_t)(kb + b_kb_off));
                    LDSM_X4(bkh[0], bkh[1], bkh[2], bkh[3], sb + ATT_KH + swB);
                    LDSM_X4(bkl[0], bkl[1], bkl[2], bkl[3], sb + ATT_KL + swB);
#pragma unroll
                    for (int s = 0; s < 2; s++) {
                        float* c = sacc[jp * 2 + s];
                        mma_bf16(c, aqh, bkh[s * 2], bkh[s * 2 + 1]);
                        mma_bf16(c, aqh, bkl[s * 2], bkl[s * 2 + 1]);
                        mma_bf16(c, aql, bkh[s * 2], bkh[s * 2 + 1]);
                    }
                }
            }

            // ---- causal mask (diagonal-straddling tiles only) ----
            if (j0 + 63 > wrow) {
                const int row0 = wrow + (lane >> 2);
#pragma unroll
                for (int j = 0; j < 8; j++) {
                    const int col = j0 + j * 8 + (lane & 3) * 2;
                    if (col > row0)         sacc[j][0] = -1e30f;
                    if (col + 1 > row0)     sacc[j][1] = -1e30f;
                    if (col > row0 + 8)     sacc[j][2] = -1e30f;
                    if (col + 1 > row0 + 8) sacc[j][3] = -1e30f;
                }
            }

            // ---- online softmax (log2 domain) ----
            float mx0 = -1e30f, mx1 = -1e30f;
#pragma unroll
            for (int j = 0; j < 8; j++) {
                mx0 = fmaxf(mx0, fmaxf(sacc[j][0], sacc[j][1]));
                mx1 = fmaxf(mx1, fmaxf(sacc[j][2], sacc[j][3]));
            }
            mx0 = fmaxf(mx0, __shfl_xor_sync(0xffffffffu, mx0, 1));
            mx0 = fmaxf(mx0, __shfl_xor_sync(0xffffffffu, mx0, 2));
            mx1 = fmaxf(mx1, __shfl_xor_sync(0xffffffffu, mx1, 1));
            mx1 = fmaxf(mx1, __shfl_xor_sync(0xffffffffu, mx1, 2));

            const float nm0 = fmaxf(mrow[0], mx0);
            const float nm1 = fmaxf(mrow[1], mx1);
            const float corr0 = fexp2(mrow[0] - nm0);
            const float corr1 = fexp2(mrow[1] - nm1);
            mrow[0] = nm0; mrow[1] = nm1;

            float sum0 = 0.f, sum1 = 0.f;
#pragma unroll
            for (int j = 0; j < 8; j++) {
                sacc[j][0] = fexp2(sacc[j][0] - nm0);
                sacc[j][1] = fexp2(sacc[j][1] - nm0);
                sacc[j][2] = fexp2(sacc[j][2] - nm1);
                sacc[j][3] = fexp2(sacc[j][3] - nm1);
                sum0 += sacc[j][0] + sacc[j][1];
                sum1 += sacc[j][2] + sacc[j][3];
            }
            sum0 += __shfl_xor_sync(0xffffffffu, sum0, 1);
            sum0 += __shfl_xor_sync(0xffffffffu, sum0, 2);
            sum1 += __shfl_xor_sync(0xffffffffu, sum1, 1);
            sum1 += __shfl_xor_sync(0xffffffffu, sum1, 2);
            lrow[0] = lrow[0] * corr0 + sum0;
            lrow[1] = lrow[1] * corr1 + sum1;

#pragma unroll
            for (int j = 0; j < 8; j++) {
                oacc[j][0] *= corr0; oacc[j][1] *= corr0;
                oacc[j][2] *= corr1; oacc[j][3] *= corr1;
            }

            // ---- O += P V (bf16x3, P packed from registers) ----
#pragma unroll
            for (int ks = 0; ks < 4; ks++) {
                uint32_t ph[4], pl[4];
                split2(sacc[2 * ks][0],     sacc[2 * ks][1],     ph[0], pl[0]);
                split2(sacc[2 * ks][2],     sacc[2 * ks][3],     ph[1], pl[1]);
                split2(sacc[2 * ks + 1][0], sacc[2 * ks + 1][1], ph[2], pl[2]);
                split2(sacc[2 * ks + 1][2], sacc[2 * ks + 1][3], ph[3], pl[3]);
#pragma unroll
                for (int ndp = 0; ndp < 4; ndp++) {
                    uint32_t bvh[4], bvl[4];
                    const uint32_t swV = swz((uint32_t)((ks * 16 + v_s_off) << 7)
                                             + (uint32_t)(ndp * 32 + v_d_off));
                    LDSM_X4_T(bvh[0], bvh[1], bvh[2], bvh[3], sb + ATT_VH + swV);
                    LDSM_X4_T(bvl[0], bvl[1], bvl[2], bvl[3], sb + ATT_VL + swV);
#pragma unroll
                    for (int s = 0; s < 2; s++) {
                        float* c = oacc[ndp * 2 + s];
                        mma_bf16(c, ph, bvh[s * 2], bvh[s * 2 + 1]);
                        mma_bf16(c, ph, bvl[s * 2], bvl[s * 2 + 1]);
                        mma_bf16(c, pl, bvh[s * 2], bvh[s * 2 + 1]);
                    }
                }
            }
        }

        __syncthreads();
        if (jt + 2 < ntiles) issue_kv(jt + 2, jt & 1);
    }

    // ---- epilogue: normalize, split to bf16 hi/lo, write concat layout ----
    const float inv0 = 1.f / lrow[0];
    const float inv1 = 1.f / lrow[1];
    const int row0 = q0 + wid * 16 + (lane >> 2);
#pragma unroll
    for (int j = 0; j < 8; j++) {
        const int c = h * ND + j * 8 + (lane & 3) * 2;
        uint32_t hv, lv;
        split2(oacc[j][0] * inv0, oacc[j][1] * inv0, hv, lv);
        size_t idx = ((size_t)b * NT + row0) * NC + c;
        *(uint32_t*)(g_ah + idx) = hv;
        *(uint32_t*)(g_al + idx) = lv;
        split2(oacc[j][2] * inv1, oacc[j][3] * inv1, hv, lv);
        idx = ((size_t)b * NT + row0 + 8) * NC + c;
        *(uint32_t*)(g_ah + idx) = hv;
        *(uint32_t*)(g_al + idx) = lv;
    }
}

// ---------------------------------------------------------------------------
extern "C" void kernel_launch(void* const* d_in, const int* in_sizes, int n_in,
                              void* d_out, int out_size)
{
    const float* x  = (const float*)d_in[0];
    const float* Wq = (const float*)d_in[1];
    const float* Wk = (const float*)d_in[2];
    const float* Wv = (const float*)d_in[3];
    const float* Wo = (const float*)d_in[4];
    float* out = (float*)d_out;
    (void)in_sizes; (void)n_in; (void)out_size;

    cudaFuncSetAttribute(qkv_gemm, cudaFuncAttributeMaxDynamicSharedMemorySize,
                         SMEM_GEMM_TOTAL);
    cudaFuncSetAttribute(proj_gemm, cudaFuncAttributeMaxDynamicSharedMemorySize,
                         SMEM_GEMM_TOTAL);
    cudaFuncSetAttribute(attn_mma, cudaFuncAttributeMaxDynamicSharedMemorySize,
                         ATT_SMEM);

    __nv_bfloat16 *xh, *xl, *woh, *wol;
    cudaGetSymbolAddress((void**)&xh,  g_xh);
    cudaGetSymbolAddress((void**)&xl,  g_xl);
    cudaGetSymbolAddress((void**)&woh, g_woh);
    cudaGetSymbolAddress((void**)&wol, g_wol);

    // Prep: bf16 splits (x, Wo) + W transpose-split
    split_kernel<<<2048, 256>>>(x, xh, xl, (NM * NC) / 4);
    split_kernel<<<1024, 256>>>(Wo, woh, wol, (NC * NC) / 4);
    wtsplit_kernel<<<dim3(NC / 32, ND / 32, 3 * NH), dim3(32, 8)>>>(Wq, Wk, Wv);

    // QKV projection (HMMA bf16x3, cp.async pipelined)
    qkv_gemm<<<dim3(NM / 128, NH / 2, 3), 256, SMEM_GEMM_TOTAL>>>();

    // Attention (HMMA bf16x3 flash, cp.async pipelined K/V)
    attn_mma<<<dim3(NT / 128, NH, NB), 256, ATT_SMEM>>>();

    // Output projection (HMMA bf16x3, cp.async pipelined)
    proj_gemm<<<dim3(NM / 128, NC / 128), 256, SMEM_GEMM_TOTAL>>>(out);
}